// round 15
// baseline (speedup 1.0000x reference)
#include <cuda_runtime.h>
#include <cuda_fp16.h>
#include <cstdint>
#include <math.h>

#define SEQ 4096
#define DIM 2048
#define NH 16
#define DH 128
#define D2 (DIM / 2)            // u32 (half2) per row

// Scratch (static device arrays — no allocations allowed)
__device__ float    g_q[SEQ * DIM];      // Q proj (fp32, pre-norm)
__device__ float    g_k[SEQ * DIM];      // K proj (fp32, pre-norm)
__device__ unsigned g_xh[SEQ * D2];      // x half-packed [row][k2]
__device__ unsigned g_qh[SEQ * D2];      // q half-packed, scaled by log2e/sqrt(dh)
__device__ unsigned g_kh[SEQ * D2];      // k half-packed (post norm+rope)
__device__ __half   g_vt[(size_t)DIM * SEQ];   // V transposed [dimcol][token]
__device__ unsigned g_ath[SEQ * D2];     // attention out half-packed [row][k2]
__device__ unsigned g_wp[(size_t)4 * DIM * D2];  // W^T half-packed [mat][n][k2]

__device__ __forceinline__ unsigned h2u(__half2 h) { return *(unsigned*)&h; }

__device__ __forceinline__ float ex2(float x) {
    float r; asm("ex2.approx.f32 %0, %1;" : "=f"(r) : "f"(x)); return r;
}

__device__ __forceinline__ void mma_f16(float* c, const unsigned* a, const unsigned* b) {
    asm volatile(
        "mma.sync.aligned.m16n8k16.row.col.f32.f16.f16.f32 "
        "{%0,%1,%2,%3}, {%4,%5,%6,%7}, {%8,%9}, {%0,%1,%2,%3};\n"
        : "+f"(c[0]), "+f"(c[1]), "+f"(c[2]), "+f"(c[3])
        : "r"(a[0]), "r"(a[1]), "r"(a[2]), "r"(a[3]), "r"(b[0]), "r"(b[1]));
}

__device__ __forceinline__ void ldsm4(unsigned& r0, unsigned& r1, unsigned& r2,
                                      unsigned& r3, unsigned addr) {
    asm volatile("ldmatrix.sync.aligned.m8n8.x4.shared.b16 {%0,%1,%2,%3}, [%4];\n"
        : "=r"(r0), "=r"(r1), "=r"(r2), "=r"(r3) : "r"(addr));
}

__device__ __forceinline__ void cpa16(void* dst, const void* src) {
    unsigned d = (unsigned)__cvta_generic_to_shared(dst);
    asm volatile("cp.async.cg.shared.global [%0], [%1], 16;\n" :: "r"(d), "l"(src));
}
#define CP_COMMIT() asm volatile("cp.async.commit_group;\n" ::: "memory")
#define CP_WAIT1()  asm volatile("cp.async.wait_group 1;\n" ::: "memory")
#define CP_WAIT0()  asm volatile("cp.async.wait_group 0;\n" ::: "memory")

// ---------------------------------------------------------------------------
// Producers: pack x and W (transposed, k-pairs per column)
// ---------------------------------------------------------------------------
__global__ void pack_x_kernel(const float* __restrict__ x) {
    int i = blockIdx.x * blockDim.x + threadIdx.x;
    int stride = gridDim.x * blockDim.x;
    for (; i < SEQ * D2; i += stride) {
        float2 v = ((const float2*)x)[i];
        g_xh[i] = h2u(__floats2half2_rn(v.x, v.y));
    }
}

__global__ void packw_kernel(const float* __restrict__ Wq, const float* __restrict__ Wk,
                             const float* __restrict__ Wv, const float* __restrict__ Wo) {
    __shared__ float sm[32][33];
    const float* W;
    if (blockIdx.z == 0)      W = Wq;
    else if (blockIdx.z == 1) W = Wk;
    else if (blockIdx.z == 2) W = Wv;
    else                      W = Wo;
    unsigned* out = g_wp + (size_t)blockIdx.z * DIM * D2;
    const int k0 = blockIdx.x * 32, n0 = blockIdx.y * 32;
    const int tx = threadIdx.x & 31, ty = threadIdx.x >> 5;
#pragma unroll
    for (int i = 0; i < 4; i++)
        sm[ty + i * 8][tx] = W[(size_t)(k0 + ty + i * 8) * DIM + n0 + tx];
    __syncthreads();
    int idx = threadIdx.x;
#pragma unroll
    for (int p = 0; p < 2; p++, idx += 256) {
        int nl = idx >> 4, c = idx & 15;
        out[(size_t)(n0 + nl) * D2 + (k0 >> 1) + c] =
            h2u(__floats2half2_rn(sm[2 * c][nl], sm[2 * c + 1][nl]));
    }
}

// ---------------------------------------------------------------------------
// fp16 GEMM (unchanged from R14 — passing): BM=128, BN=128, BK=64, 3-stage
// cp.async, 8 warps (64x32 each), 2 CTAs/SM, ldmatrix fragments.
// ---------------------------------------------------------------------------
#define BM 128
#define BN 128
#define BK2 32
#define AST 36
#define BST 36
#define ASTG (BM * AST)
#define BSTG (BN * BST)
#define GEMM_SMEM (3 * (ASTG + BSTG) * 4)   // 110592 B
#define NKT (D2 / BK2)

__device__ __forceinline__ void gemm_issue(unsigned* As, unsigned* Bs, int kt,
                                           const unsigned* Ag, const unsigned* Bg, int tid) {
    const int stg = kt % 3;
    const int k2 = kt * BK2;
    unsigned* Ad = As + stg * ASTG;
    unsigned* Bd = Bs + stg * BSTG;
#pragma unroll
    for (int i = 0; i < 4; i++) {
        int idx = tid + i * 256;
        int r = idx >> 3, c = (idx & 7) * 4;
        cpa16(Ad + r * AST + c, Ag + (size_t)r * D2 + k2 + c);
    }
#pragma unroll
    for (int i = 0; i < 4; i++) {
        int idx = tid + i * 256;
        int r = idx >> 3, c = (idx & 7) * 4;
        cpa16(Bd + r * BST + c, Bg + (size_t)r * D2 + k2 + c);
    }
}

__device__ __forceinline__ void gemm_mainloop(const unsigned* Ag, const unsigned* Bg,
                                              unsigned* As, unsigned* Bs,
                                              float c[4][4][4], int tid) {
    const int lane = tid & 31, wid = tid >> 5;
    const int wm = (wid & 1) * 64;
    const int wn = (wid >> 1) * 32;

    const unsigned afoff =
        (unsigned)((wm + (lane & 15)) * AST + ((lane >> 4) << 2)) * 4;
    const int brow = (lane & 7) | ((lane >> 4) << 3);
    const int bcol = (lane & 8) >> 1;
    const unsigned bfoff = (unsigned)((wn + brow) * BST + bcol) * 4;

    const unsigned abase0 = (unsigned)__cvta_generic_to_shared(As) + afoff;
    const unsigned bbase0 = (unsigned)__cvta_generic_to_shared(Bs) + bfoff;

#pragma unroll
    for (int mt = 0; mt < 4; mt++)
#pragma unroll
        for (int nt = 0; nt < 4; nt++)
#pragma unroll
            for (int i = 0; i < 4; i++) c[mt][nt][i] = 0.f;

    gemm_issue(As, Bs, 0, Ag, Bg, tid); CP_COMMIT();
    gemm_issue(As, Bs, 1, Ag, Bg, tid); CP_COMMIT();

    for (int kt = 0; kt < NKT; kt++) {
        CP_WAIT1();
        __syncthreads();
        if (kt + 2 < NKT) gemm_issue(As, Bs, kt + 2, Ag, Bg, tid);
        CP_COMMIT();

        const int buf = kt % 3;
        const unsigned abase = abase0 + (unsigned)(buf * ASTG) * 4;
        const unsigned bbase = bbase0 + (unsigned)(buf * BSTG) * 4;
#pragma unroll
        for (int kk2 = 0; kk2 < BK2; kk2 += 8) {
            unsigned a[4][4];
#pragma unroll
            for (int mt = 0; mt < 4; mt++)
                ldsm4(a[mt][0], a[mt][1], a[mt][2], a[mt][3],
                      abase + (unsigned)(mt * 16 * AST + kk2) * 4);
#pragma unroll
            for (int n2 = 0; n2 < 2; n2++) {
                unsigned b[4];
                ldsm4(b[0], b[1], b[2], b[3],
                      bbase + (unsigned)(n2 * 16 * BST + kk2) * 4);
#pragma unroll
                for (int mt = 0; mt < 4; mt++) {
                    mma_f16(c[mt][2 * n2],     a[mt], b);
                    mma_f16(c[mt][2 * n2 + 1], a[mt], b + 2);
                }
            }
        }
    }
}

__global__ __launch_bounds__(256, 2)
void gemm_qkv_kernel(const float* __restrict__ bq, const float* __restrict__ bk,
                     const float* __restrict__ bv) {
    extern __shared__ unsigned gsm[];
    const int tid = threadIdx.x;
    const int lane = tid & 31, wid = tid >> 5;
    const int wm = (wid & 1) * 64, wn = (wid >> 1) * 32;
    const int g = lane >> 2, t = lane & 3;
    const int z = blockIdx.z;

    const unsigned* Ag = g_xh + (size_t)(blockIdx.y * BM) * D2;
    const unsigned* Bg = g_wp + (size_t)z * DIM * D2 + (size_t)(blockIdx.x * BN) * D2;

    float c[4][4][4];
    gemm_mainloop(Ag, Bg, gsm, gsm + 3 * ASTG, c, tid);

    const int rowB = blockIdx.y * BM + wm;
    const int colB = blockIdx.x * BN + wn;
    const float* bias = (z == 0) ? bq : (z == 1) ? bk : bv;

    if (z < 2) {
        float* C = (z == 0) ? g_q : g_k;
#pragma unroll
        for (int mt = 0; mt < 4; mt++) {
            int r0 = rowB + mt * 16 + g;
#pragma unroll
            for (int nt = 0; nt < 4; nt++) {
                int col = colB + nt * 8 + 2 * t;
                float b0 = bias[col], b1 = bias[col + 1];
                float2 v;
                v.x = c[mt][nt][0] + b0; v.y = c[mt][nt][1] + b1;
                *(float2*)(C + (size_t)r0 * DIM + col) = v;
                v.x = c[mt][nt][2] + b0; v.y = c[mt][nt][3] + b1;
                *(float2*)(C + (size_t)(r0 + 8) * DIM + col) = v;
            }
        }
    } else {
#pragma unroll
        for (int mt = 0; mt < 4; mt++) {
            int r0 = rowB + mt * 16 + g;
#pragma unroll
            for (int nt = 0; nt < 4; nt++) {
                int col = colB + nt * 8 + 2 * t;
                float b0 = bias[col], b1 = bias[col + 1];
                g_vt[(size_t)col * SEQ + r0]           = __float2half(c[mt][nt][0] + b0);
                g_vt[(size_t)(col + 1) * SEQ + r0]     = __float2half(c[mt][nt][1] + b1);
                g_vt[(size_t)col * SEQ + r0 + 8]       = __float2half(c[mt][nt][2] + b0);
                g_vt[(size_t)(col + 1) * SEQ + r0 + 8] = __float2half(c[mt][nt][3] + b1);
            }
        }
    }
}

__global__ __launch_bounds__(256, 2)
void gemm_proj_kernel(const float* __restrict__ bias, float* __restrict__ C) {
    extern __shared__ unsigned gsm[];
    const int tid = threadIdx.x;
    const int lane = tid & 31, wid = tid >> 5;
    const int wm = (wid & 1) * 64, wn = (wid >> 1) * 32;
    const int g = lane >> 2, t = lane & 3;

    const unsigned* Ag = g_ath + (size_t)(blockIdx.y * BM) * D2;
    const unsigned* Bg = g_wp + (size_t)3 * DIM * D2 + (size_t)(blockIdx.x * BN) * D2;

    float c[4][4][4];
    gemm_mainloop(Ag, Bg, gsm, gsm + 3 * ASTG, c, tid);

    const int rowB = blockIdx.y * BM + wm;
    const int colB = blockIdx.x * BN + wn;
#pragma unroll
    for (int mt = 0; mt < 4; mt++) {
        int r0 = rowB + mt * 16 + g;
#pragma unroll
        for (int nt = 0; nt < 4; nt++) {
            int col = colB + nt * 8 + 2 * t;
            float b0 = bias[col], b1 = bias[col + 1];
            float2 v;
            v.x = c[mt][nt][0] + b0; v.y = c[mt][nt][1] + b1;
            *(float2*)(C + (size_t)r0 * DIM + col) = v;
            v.x = c[mt][nt][2] + b0; v.y = c[mt][nt][3] + b1;
            *(float2*)(C + (size_t)(r0 + 8) * DIM + col) = v;
        }
    }
}

// ---------------------------------------------------------------------------
// RMSNorm + RoPE (unchanged): q pre-scaled by log2(e)/sqrt(DH)
// ---------------------------------------------------------------------------
__global__ __launch_bounds__(256)
void rmsnorm_rope_kernel(const float* __restrict__ fc, const float* __restrict__ fs,
                         const float* __restrict__ gq, const float* __restrict__ gk) {
    const int s = blockIdx.x;
    const int tid = threadIdx.x;
    const float* qrow = g_q + (size_t)s * DIM;
    const float* krow = g_k + (size_t)s * DIM;
    const float qscale = 0.08838834764831845f * 1.4426950408889634f;

    float q1[4], q2[4], k1[4], k2[4];
    float sq = 0.f, sk = 0.f;
#pragma unroll
    for (int j = 0; j < 4; j++) {
        int p = tid + j * 256;
        int h = p >> 6, jj = p & 63;
        int i1 = h * DH + 2 * jj;
        float2 qv = *(const float2*)(qrow + i1);
        float2 kv = *(const float2*)(krow + i1);
        q1[j] = qv.x; q2[j] = qv.y; k1[j] = kv.x; k2[j] = kv.y;
        sq += qv.x * qv.x + qv.y * qv.y;
        sk += kv.x * kv.x + kv.y * kv.y;
    }
#pragma unroll
    for (int off = 16; off > 0; off >>= 1) {
        sq += __shfl_xor_sync(0xffffffffu, sq, off);
        sk += __shfl_xor_sync(0xffffffffu, sk, off);
    }
    __shared__ float sh[16];
    if ((tid & 31) == 0) { sh[tid >> 5] = sq; sh[8 + (tid >> 5)] = sk; }
    __syncthreads();
    float tq = 0.f, tk = 0.f;
#pragma unroll
    for (int w = 0; w < 8; w++) { tq += sh[w]; tk += sh[8 + w]; }
    const float rq = rsqrtf(tq * (1.0f / DIM) + 1e-5f);
    const float rk = rsqrtf(tk * (1.0f / DIM) + 1e-5f);

#pragma unroll
    for (int j = 0; j < 4; j++) {
        int p = tid + j * 256;
        int h = p >> 6, jj = p & 63;
        int i1 = h * DH + 2 * jj;
        float c = fc[(size_t)s * DH + 2 * jj];
        float sn = fs[(size_t)s * DH + 2 * jj + 1];
        float x1 = q1[j] * rq * gq[i1];
        float x2 = q2[j] * rq * gq[i1 + 1];
        g_qh[(size_t)s * D2 + (i1 >> 1)] =
            h2u(__floats2half2_rn((x1 * c - x2 * sn) * qscale,
                                  (x1 * sn + x2 * c) * qscale));
        x1 = k1[j] * rk * gk[i1];
        x2 = k2[j] * rk * gk[i1 + 1];
        g_kh[(size_t)s * D2 + (i1 >> 1)] =
            h2u(__floats2half2_rn(x1 * c - x2 * sn, x1 * sn + x2 * c));
    }
}

// ---------------------------------------------------------------------------
// Flash attention: fp16 m16n8k16, BQ=64, BKV=64, 128 threads, 2 CTAs/SM.
// STATIC-BASE softmax: P = 2^(s2 - 6), no running max, no rescaling, l is a
// plain accumulator reduced once at the end. Bound: |s_nats| <= 11.3 ->
// s2 <= 16.3, P <= 2^10.3 << fp16 max. Uniform 2^-6 cancels in o/l.
// ---------------------------------------------------------------------------
#define BQ 64
#define BKV 64
#define NTHR 128
#define KS2 68
#define VS2 36
#define PS2 36
#define KSTG2 (BKV * KS2)
#define ATTN_SMEM ((2 * KSTG2 + DH * VS2 + BQ * PS2) * 4)   // 62464 B
#define NT (SEQ / BKV)

__global__ __launch_bounds__(NTHR, 2)
void attn_kernel() {
    extern __shared__ unsigned smu[];
    unsigned* K0 = smu;
    unsigned* Vs = K0 + 2 * KSTG2;
    unsigned* Ps = Vs + DH * VS2;

    const int h = blockIdx.y;
    const int q0 = blockIdx.x * BQ;
    const int tid = threadIdx.x;
    const int lane = tid & 31, wid = tid >> 5;
    const int g = lane >> 2, t = lane & 3;
    const int rbase = wid * 16;
    const unsigned* vt32 = (const unsigned*)g_vt;

    const int brow = (lane & 7) | ((lane >> 4) << 3);
    const int bcol = (lane & 8) >> 1;
    const unsigned kfoff = (unsigned)(brow * KS2 + bcol) * 4;
    const unsigned vfoff = (unsigned)(brow * VS2 + bcol) * 4;
    const unsigned pfoff = (unsigned)((rbase + (lane & 15)) * PS2 + ((lane >> 4) << 2)) * 4;

    const unsigned kbase = (unsigned)__cvta_generic_to_shared(K0);
    const unsigned vbase = (unsigned)__cvta_generic_to_shared(Vs) + vfoff;
    const unsigned pbase = (unsigned)__cvta_generic_to_shared(Ps) + pfoff;

    // prologue: K(0) -> buf0
#pragma unroll
    for (int i = 0; i < 8; i++) {
        int idx = tid + i * NTHR;
        int r = idx >> 4, c = (idx & 15) * 4;
        cpa16(K0 + r * KS2 + c, g_kh + (size_t)r * D2 + h * 64 + c);
    }
    CP_COMMIT();

    unsigned qf[8][4];
    {
        const unsigned* qr0 = g_qh + (size_t)(q0 + rbase + g) * D2 + h * 64;
        const unsigned* qr1 = qr0 + 8 * D2;
#pragma unroll
        for (int ks = 0; ks < 8; ks++) {
            int kk2 = ks * 8;
            qf[ks][0] = qr0[kk2 + t];
            qf[ks][1] = qr1[kk2 + t];
            qf[ks][2] = qr0[kk2 + t + 4];
            qf[ks][3] = qr1[kk2 + t + 4];
        }
    }

    float o[16][4];
#pragma unroll
    for (int nt = 0; nt < 16; nt++)
#pragma unroll
        for (int i = 0; i < 4; i++) o[nt][i] = 0.f;
    float l0 = 0.f, l1 = 0.f;     // plain accumulators (no rescaling)

    for (int kt = 0; kt < NT; kt++) {
        CP_WAIT0();
        __syncthreads();
        const int tok0 = kt * BKV;

#pragma unroll
        for (int i = 0; i < 8; i++) {
            int idx = tid + i * NTHR;
            int r = idx >> 3, c = (idx & 7) * 4;
            cpa16(Vs + r * VS2 + c,
                  vt32 + (size_t)(h * DH + r) * (SEQ / 2) + (tok0 >> 1) + c);
        }
        CP_COMMIT();
        if (kt + 1 < NT) {
            unsigned* Kn = K0 + ((kt + 1) & 1) * KSTG2;
#pragma unroll
            for (int i = 0; i < 8; i++) {
                int idx = tid + i * NTHR;
                int r = idx >> 4, c = (idx & 15) * 4;
                cpa16(Kn + r * KS2 + c,
                      g_kh + (size_t)(tok0 + BKV + r) * D2 + h * 64 + c);
            }
        }
        CP_COMMIT();

        const unsigned kb = kbase + ((kt & 1) ? KSTG2 * 4u : 0u) + kfoff;

        // ---- S = Q K^T ----
        float s[8][4];
#pragma unroll
        for (int nt = 0; nt < 8; nt++)
#pragma unroll
            for (int i = 0; i < 4; i++) s[nt][i] = 0.f;

#pragma unroll
        for (int ks = 0; ks < 8; ks++) {
#pragma unroll
            for (int n2 = 0; n2 < 4; n2++) {
                unsigned b[4];
                ldsm4(b[0], b[1], b[2], b[3],
                      kb + (unsigned)(n2 * 16 * KS2 + ks * 8) * 4);
                mma_f16(s[2 * n2],     qf[ks], b);
                mma_f16(s[2 * n2 + 1], qf[ks], b + 2);
            }
        }

        // ---- static-base softmax: P = 2^(s - 6) ----
#pragma unroll
        for (int nt = 0; nt < 8; nt++) {
            float p00 = ex2(s[nt][0] - 6.0f);
            float p01 = ex2(s[nt][1] - 6.0f);
            float p10 = ex2(s[nt][2] - 6.0f);
            float p11 = ex2(s[nt][3] - 6.0f);
            l0 += p00 + p01; l1 += p10 + p11;
            Ps[(rbase + g) * PS2 + nt * 4 + t]     = h2u(__floats2half2_rn(p00, p01));
            Ps[(rbase + g + 8) * PS2 + nt * 4 + t] = h2u(__floats2half2_rn(p10, p11));
        }

        CP_WAIT1();
        __syncthreads();

        // ---- O += P V ----
#pragma unroll
        for (int ks = 0; ks < 4; ks++) {
            unsigned a[4];
            ldsm4(a[0], a[1], a[2], a[3], pbase + (unsigned)(ks * 8) * 4);
#pragma unroll
            for (int n2 = 0; n2 < 8; n2++) {
                unsigned b[4];
                ldsm4(b[0], b[1], b[2], b[3],
                      vbase + (unsigned)(n2 * 16 * VS2 + ks * 8) * 4);
                mma_f16(o[2 * n2],     a, b);
                mma_f16(o[2 * n2 + 1], a, b + 2);
            }
        }
    }

    // one-time row-sum reduction across the t-quad
    l0 += __shfl_xor_sync(0xffffffffu, l0, 1);
    l0 += __shfl_xor_sync(0xffffffffu, l0, 2);
    l1 += __shfl_xor_sync(0xffffffffu, l1, 1);
    l1 += __shfl_xor_sync(0xffffffffu, l1, 2);

    const float inv0 = 1.0f / l0, inv1 = 1.0f / l1;
    const int r0 = q0 + rbase + g, r1 = r0 + 8;
#pragma unroll
    for (int nt = 0; nt < 16; nt++) {
        int c2 = h * 64 + nt * 4 + t;
        g_ath[(size_t)r0 * D2 + c2] =
            h2u(__floats2half2_rn(o[nt][0] * inv0, o[nt][1] * inv0));
        g_ath[(size_t)r1 * D2 + c2] =
            h2u(__floats2half2_rn(o[nt][2] * inv1, o[nt][3] * inv1));
    }
}

// ---------------------------------------------------------------------------
// Host launch
// ---------------------------------------------------------------------------
extern "C" void kernel_launch(void* const* d_in, const int* in_sizes, int n_in,
                              void* d_out, int out_size) {
    const float* x  = (const float*)d_in[0];
    const float* fc = (const float*)d_in[1];
    const float* fs = (const float*)d_in[2];
    const float* Wq = (const float*)d_in[3];
    const float* bq = (const float*)d_in[4];
    const float* Wk = (const float*)d_in[5];
    const float* bk = (const float*)d_in[6];
    const float* Wv = (const float*)d_in[7];
    const float* bv = (const float*)d_in[8];
    const float* Wo = (const float*)d_in[9];
    const float* bo = (const float*)d_in[10];
    const float* gq = (const float*)d_in[11];
    const float* gk = (const float*)d_in[12];
    float* out = (float*)d_out;

    cudaFuncSetAttribute(gemm_qkv_kernel, cudaFuncAttributeMaxDynamicSharedMemorySize,
                         GEMM_SMEM);
    cudaFuncSetAttribute(gemm_proj_kernel, cudaFuncAttributeMaxDynamicSharedMemorySize,
                         GEMM_SMEM);
    cudaFuncSetAttribute(attn_kernel, cudaFuncAttributeMaxDynamicSharedMemorySize,
                         ATTN_SMEM);

    pack_x_kernel<<<1024, 256>>>(x);
    packw_kernel<<<dim3(DIM / 32, DIM / 32, 4), 256>>>(Wq, Wk, Wv, Wo);

    gemm_qkv_kernel<<<dim3(DIM / BN, SEQ / BM, 3), 256, GEMM_SMEM>>>(bq, bk, bv);
    rmsnorm_rope_kernel<<<SEQ, 256>>>(fc, fs, gq, gk);
    attn_kernel<<<dim3(SEQ / BQ, NH), NTHR, ATTN_SMEM>>>();
    gemm_proj_kernel<<<dim3(DIM / BN, SEQ / BM), 256, GEMM_SMEM>>>(bo, out);
}

// round 16
// speedup vs baseline: 1.4831x; 1.4831x over previous
#include <cuda_runtime.h>
#include <cuda_fp16.h>
#include <cstdint>
#include <math.h>

#define SEQ 4096
#define DIM 2048
#define NH 16
#define DH 128
#define D2 (DIM / 2)            // u32 (half2) per row

// Scratch (static device arrays — no allocations allowed)
__device__ float    g_q[SEQ * DIM];      // Q proj (fp32, pre-norm)
__device__ float    g_k[SEQ * DIM];      // K proj (fp32, pre-norm)
__device__ unsigned g_xh[SEQ * D2];      // x half-packed [row][k2]
__device__ unsigned g_qh[SEQ * D2];      // q half-packed, scaled by log2e/sqrt(dh)
__device__ unsigned g_kh[SEQ * D2];      // k half-packed (post norm+rope)
__device__ __half   g_vt[(size_t)DIM * SEQ];   // V transposed [dimcol][token]
__device__ unsigned g_ath[SEQ * D2];     // attention out half-packed [row][k2]
__device__ unsigned g_wp[(size_t)4 * DIM * D2];  // W^T half-packed [mat][n][k2]

__device__ __forceinline__ unsigned h2u(__half2 h) { return *(unsigned*)&h; }

__device__ __forceinline__ float ex2(float x) {
    float r; asm("ex2.approx.f32 %0, %1;" : "=f"(r) : "f"(x)); return r;
}

__device__ __forceinline__ void mma_f16(float* c, const unsigned* a, const unsigned* b) {
    asm volatile(
        "mma.sync.aligned.m16n8k16.row.col.f32.f16.f16.f32 "
        "{%0,%1,%2,%3}, {%4,%5,%6,%7}, {%8,%9}, {%0,%1,%2,%3};\n"
        : "+f"(c[0]), "+f"(c[1]), "+f"(c[2]), "+f"(c[3])
        : "r"(a[0]), "r"(a[1]), "r"(a[2]), "r"(a[3]), "r"(b[0]), "r"(b[1]));
}

__device__ __forceinline__ void ldsm4(unsigned& r0, unsigned& r1, unsigned& r2,
                                      unsigned& r3, unsigned addr) {
    asm volatile("ldmatrix.sync.aligned.m8n8.x4.shared.b16 {%0,%1,%2,%3}, [%4];\n"
        : "=r"(r0), "=r"(r1), "=r"(r2), "=r"(r3) : "r"(addr));
}

__device__ __forceinline__ void cpa16(void* dst, const void* src) {
    unsigned d = (unsigned)__cvta_generic_to_shared(dst);
    asm volatile("cp.async.cg.shared.global [%0], [%1], 16;\n" :: "r"(d), "l"(src));
}
#define CP_COMMIT() asm volatile("cp.async.commit_group;\n" ::: "memory")
#define CP_WAIT1()  asm volatile("cp.async.wait_group 1;\n" ::: "memory")
#define CP_WAIT0()  asm volatile("cp.async.wait_group 0;\n" ::: "memory")

// ---------------------------------------------------------------------------
// Producers: pack x and W (transposed, k-pairs per column)
// ---------------------------------------------------------------------------
__global__ void pack_x_kernel(const float* __restrict__ x) {
    int i = blockIdx.x * blockDim.x + threadIdx.x;
    int stride = gridDim.x * blockDim.x;
    for (; i < SEQ * D2; i += stride) {
        float2 v = ((const float2*)x)[i];
        g_xh[i] = h2u(__floats2half2_rn(v.x, v.y));
    }
}

__global__ void packw_kernel(const float* __restrict__ Wq, const float* __restrict__ Wk,
                             const float* __restrict__ Wv, const float* __restrict__ Wo) {
    __shared__ float sm[32][33];
    const float* W;
    if (blockIdx.z == 0)      W = Wq;
    else if (blockIdx.z == 1) W = Wk;
    else if (blockIdx.z == 2) W = Wv;
    else                      W = Wo;
    unsigned* out = g_wp + (size_t)blockIdx.z * DIM * D2;
    const int k0 = blockIdx.x * 32, n0 = blockIdx.y * 32;
    const int tx = threadIdx.x & 31, ty = threadIdx.x >> 5;
#pragma unroll
    for (int i = 0; i < 4; i++)
        sm[ty + i * 8][tx] = W[(size_t)(k0 + ty + i * 8) * DIM + n0 + tx];
    __syncthreads();
    int idx = threadIdx.x;
#pragma unroll
    for (int p = 0; p < 2; p++, idx += 256) {
        int nl = idx >> 4, c = idx & 15;
        out[(size_t)(n0 + nl) * D2 + (k0 >> 1) + c] =
            h2u(__floats2half2_rn(sm[2 * c][nl], sm[2 * c + 1][nl]));
    }
}

// ---------------------------------------------------------------------------
// fp16 GEMM (unchanged from R14 — passing): BM=128, BN=128, BK=64, 3-stage
// cp.async, 8 warps (64x32 each), 2 CTAs/SM, ldmatrix fragments.
// ---------------------------------------------------------------------------
#define BM 128
#define BN 128
#define BK2 32
#define AST 36
#define BST 36
#define ASTG (BM * AST)
#define BSTG (BN * BST)
#define GEMM_SMEM (3 * (ASTG + BSTG) * 4)   // 110592 B
#define NKT (D2 / BK2)

__device__ __forceinline__ void gemm_issue(unsigned* As, unsigned* Bs, int kt,
                                           const unsigned* Ag, const unsigned* Bg, int tid) {
    const int stg = kt % 3;
    const int k2 = kt * BK2;
    unsigned* Ad = As + stg * ASTG;
    unsigned* Bd = Bs + stg * BSTG;
#pragma unroll
    for (int i = 0; i < 4; i++) {
        int idx = tid + i * 256;
        int r = idx >> 3, c = (idx & 7) * 4;
        cpa16(Ad + r * AST + c, Ag + (size_t)r * D2 + k2 + c);
    }
#pragma unroll
    for (int i = 0; i < 4; i++) {
        int idx = tid + i * 256;
        int r = idx >> 3, c = (idx & 7) * 4;
        cpa16(Bd + r * BST + c, Bg + (size_t)r * D2 + k2 + c);
    }
}

__device__ __forceinline__ void gemm_mainloop(const unsigned* Ag, const unsigned* Bg,
                                              unsigned* As, unsigned* Bs,
                                              float c[4][4][4], int tid) {
    const int lane = tid & 31, wid = tid >> 5;
    const int wm = (wid & 1) * 64;
    const int wn = (wid >> 1) * 32;

    const unsigned afoff =
        (unsigned)((wm + (lane & 15)) * AST + ((lane >> 4) << 2)) * 4;
    const int brow = (lane & 7) | ((lane >> 4) << 3);
    const int bcol = (lane & 8) >> 1;
    const unsigned bfoff = (unsigned)((wn + brow) * BST + bcol) * 4;

    const unsigned abase0 = (unsigned)__cvta_generic_to_shared(As) + afoff;
    const unsigned bbase0 = (unsigned)__cvta_generic_to_shared(Bs) + bfoff;

#pragma unroll
    for (int mt = 0; mt < 4; mt++)
#pragma unroll
        for (int nt = 0; nt < 4; nt++)
#pragma unroll
            for (int i = 0; i < 4; i++) c[mt][nt][i] = 0.f;

    gemm_issue(As, Bs, 0, Ag, Bg, tid); CP_COMMIT();
    gemm_issue(As, Bs, 1, Ag, Bg, tid); CP_COMMIT();

    for (int kt = 0; kt < NKT; kt++) {
        CP_WAIT1();
        __syncthreads();
        if (kt + 2 < NKT) gemm_issue(As, Bs, kt + 2, Ag, Bg, tid);
        CP_COMMIT();

        const int buf = kt % 3;
        const unsigned abase = abase0 + (unsigned)(buf * ASTG) * 4;
        const unsigned bbase = bbase0 + (unsigned)(buf * BSTG) * 4;
#pragma unroll
        for (int kk2 = 0; kk2 < BK2; kk2 += 8) {
            unsigned a[4][4];
#pragma unroll
            for (int mt = 0; mt < 4; mt++)
                ldsm4(a[mt][0], a[mt][1], a[mt][2], a[mt][3],
                      abase + (unsigned)(mt * 16 * AST + kk2) * 4);
#pragma unroll
            for (int n2 = 0; n2 < 2; n2++) {
                unsigned b[4];
                ldsm4(b[0], b[1], b[2], b[3],
                      bbase + (unsigned)(n2 * 16 * BST + kk2) * 4);
#pragma unroll
                for (int mt = 0; mt < 4; mt++) {
                    mma_f16(c[mt][2 * n2],     a[mt], b);
                    mma_f16(c[mt][2 * n2 + 1], a[mt], b + 2);
                }
            }
        }
    }
}

__global__ __launch_bounds__(256, 2)
void gemm_qkv_kernel(const float* __restrict__ bq, const float* __restrict__ bk,
                     const float* __restrict__ bv) {
    extern __shared__ unsigned gsm[];
    const int tid = threadIdx.x;
    const int lane = tid & 31, wid = tid >> 5;
    const int wm = (wid & 1) * 64, wn = (wid >> 1) * 32;
    const int g = lane >> 2, t = lane & 3;
    const int z = blockIdx.z;

    const unsigned* Ag = g_xh + (size_t)(blockIdx.y * BM) * D2;
    const unsigned* Bg = g_wp + (size_t)z * DIM * D2 + (size_t)(blockIdx.x * BN) * D2;

    float c[4][4][4];
    gemm_mainloop(Ag, Bg, gsm, gsm + 3 * ASTG, c, tid);

    const int rowB = blockIdx.y * BM + wm;
    const int colB = blockIdx.x * BN + wn;
    const float* bias = (z == 0) ? bq : (z == 1) ? bk : bv;

    if (z < 2) {
        float* C = (z == 0) ? g_q : g_k;
#pragma unroll
        for (int mt = 0; mt < 4; mt++) {
            int r0 = rowB + mt * 16 + g;
#pragma unroll
            for (int nt = 0; nt < 4; nt++) {
                int col = colB + nt * 8 + 2 * t;
                float b0 = bias[col], b1 = bias[col + 1];
                float2 v;
                v.x = c[mt][nt][0] + b0; v.y = c[mt][nt][1] + b1;
                *(float2*)(C + (size_t)r0 * DIM + col) = v;
                v.x = c[mt][nt][2] + b0; v.y = c[mt][nt][3] + b1;
                *(float2*)(C + (size_t)(r0 + 8) * DIM + col) = v;
            }
        }
    } else {
#pragma unroll
        for (int mt = 0; mt < 4; mt++) {
            int r0 = rowB + mt * 16 + g;
#pragma unroll
            for (int nt = 0; nt < 4; nt++) {
                int col = colB + nt * 8 + 2 * t;
                float b0 = bias[col], b1 = bias[col + 1];
                g_vt[(size_t)col * SEQ + r0]           = __float2half(c[mt][nt][0] + b0);
                g_vt[(size_t)(col + 1) * SEQ + r0]     = __float2half(c[mt][nt][1] + b1);
                g_vt[(size_t)col * SEQ + r0 + 8]       = __float2half(c[mt][nt][2] + b0);
                g_vt[(size_t)(col + 1) * SEQ + r0 + 8] = __float2half(c[mt][nt][3] + b1);
            }
        }
    }
}

__global__ __launch_bounds__(256, 2)
void gemm_proj_kernel(const float* __restrict__ bias, float* __restrict__ C) {
    extern __shared__ unsigned gsm[];
    const int tid = threadIdx.x;
    const int lane = tid & 31, wid = tid >> 5;
    const int wm = (wid & 1) * 64, wn = (wid >> 1) * 32;
    const int g = lane >> 2, t = lane & 3;

    const unsigned* Ag = g_ath + (size_t)(blockIdx.y * BM) * D2;
    const unsigned* Bg = g_wp + (size_t)3 * DIM * D2 + (size_t)(blockIdx.x * BN) * D2;

    float c[4][4][4];
    gemm_mainloop(Ag, Bg, gsm, gsm + 3 * ASTG, c, tid);

    const int rowB = blockIdx.y * BM + wm;
    const int colB = blockIdx.x * BN + wn;
#pragma unroll
    for (int mt = 0; mt < 4; mt++) {
        int r0 = rowB + mt * 16 + g;
#pragma unroll
        for (int nt = 0; nt < 4; nt++) {
            int col = colB + nt * 8 + 2 * t;
            float b0 = bias[col], b1 = bias[col + 1];
            float2 v;
            v.x = c[mt][nt][0] + b0; v.y = c[mt][nt][1] + b1;
            *(float2*)(C + (size_t)r0 * DIM + col) = v;
            v.x = c[mt][nt][2] + b0; v.y = c[mt][nt][3] + b1;
            *(float2*)(C + (size_t)(r0 + 8) * DIM + col) = v;
        }
    }
}

// ---------------------------------------------------------------------------
// RMSNorm + RoPE (unchanged): q pre-scaled by log2(e)/sqrt(DH)
// ---------------------------------------------------------------------------
__global__ __launch_bounds__(256)
void rmsnorm_rope_kernel(const float* __restrict__ fc, const float* __restrict__ fs,
                         const float* __restrict__ gq, const float* __restrict__ gk) {
    const int s = blockIdx.x;
    const int tid = threadIdx.x;
    const float* qrow = g_q + (size_t)s * DIM;
    const float* krow = g_k + (size_t)s * DIM;
    const float qscale = 0.08838834764831845f * 1.4426950408889634f;

    float q1[4], q2[4], k1[4], k2[4];
    float sq = 0.f, sk = 0.f;
#pragma unroll
    for (int j = 0; j < 4; j++) {
        int p = tid + j * 256;
        int h = p >> 6, jj = p & 63;
        int i1 = h * DH + 2 * jj;
        float2 qv = *(const float2*)(qrow + i1);
        float2 kv = *(const float2*)(krow + i1);
        q1[j] = qv.x; q2[j] = qv.y; k1[j] = kv.x; k2[j] = kv.y;
        sq += qv.x * qv.x + qv.y * qv.y;
        sk += kv.x * kv.x + kv.y * kv.y;
    }
#pragma unroll
    for (int off = 16; off > 0; off >>= 1) {
        sq += __shfl_xor_sync(0xffffffffu, sq, off);
        sk += __shfl_xor_sync(0xffffffffu, sk, off);
    }
    __shared__ float sh[16];
    if ((tid & 31) == 0) { sh[tid >> 5] = sq; sh[8 + (tid >> 5)] = sk; }
    __syncthreads();
    float tq = 0.f, tk = 0.f;
#pragma unroll
    for (int w = 0; w < 8; w++) { tq += sh[w]; tk += sh[8 + w]; }
    const float rq = rsqrtf(tq * (1.0f / DIM) + 1e-5f);
    const float rk = rsqrtf(tk * (1.0f / DIM) + 1e-5f);

#pragma unroll
    for (int j = 0; j < 4; j++) {
        int p = tid + j * 256;
        int h = p >> 6, jj = p & 63;
        int i1 = h * DH + 2 * jj;
        float c = fc[(size_t)s * DH + 2 * jj];
        float sn = fs[(size_t)s * DH + 2 * jj + 1];
        float x1 = q1[j] * rq * gq[i1];
        float x2 = q2[j] * rq * gq[i1 + 1];
        g_qh[(size_t)s * D2 + (i1 >> 1)] =
            h2u(__floats2half2_rn((x1 * c - x2 * sn) * qscale,
                                  (x1 * sn + x2 * c) * qscale));
        x1 = k1[j] * rk * gk[i1];
        x2 = k2[j] * rk * gk[i1 + 1];
        g_kh[(size_t)s * D2 + (i1 >> 1)] =
            h2u(__floats2half2_rn(x1 * c - x2 * sn, x1 * sn + x2 * c));
    }
}

// ---------------------------------------------------------------------------
// Flash attention: fp16 m16n8k16, BQ=64, BKV=64, 128 threads, 2 CTAs/SM.
// R14 online softmax, with (a) per-thread l partials (quad-reduced once at
// the end; exact by the recurrence expansion) and (b) o-rescale skipped when
// both alphas == 1 (exact identity).
// ---------------------------------------------------------------------------
#define BQ 64
#define BKV 64
#define NTHR 128
#define KS2 68
#define VS2 36
#define PS2 36
#define KSTG2 (BKV * KS2)
#define ATTN_SMEM ((2 * KSTG2 + DH * VS2 + BQ * PS2) * 4)   // 62464 B
#define NT (SEQ / BKV)

__global__ __launch_bounds__(NTHR, 2)
void attn_kernel() {
    extern __shared__ unsigned smu[];
    unsigned* K0 = smu;
    unsigned* Vs = K0 + 2 * KSTG2;
    unsigned* Ps = Vs + DH * VS2;

    const int h = blockIdx.y;
    const int q0 = blockIdx.x * BQ;
    const int tid = threadIdx.x;
    const int lane = tid & 31, wid = tid >> 5;
    const int g = lane >> 2, t = lane & 3;
    const int rbase = wid * 16;
    const unsigned* vt32 = (const unsigned*)g_vt;

    const int brow = (lane & 7) | ((lane >> 4) << 3);
    const int bcol = (lane & 8) >> 1;
    const unsigned kfoff = (unsigned)(brow * KS2 + bcol) * 4;
    const unsigned vfoff = (unsigned)(brow * VS2 + bcol) * 4;
    const unsigned pfoff = (unsigned)((rbase + (lane & 15)) * PS2 + ((lane >> 4) << 2)) * 4;

    const unsigned kbase = (unsigned)__cvta_generic_to_shared(K0);
    const unsigned vbase = (unsigned)__cvta_generic_to_shared(Vs) + vfoff;
    const unsigned pbase = (unsigned)__cvta_generic_to_shared(Ps) + pfoff;

    // prologue: K(0) -> buf0
#pragma unroll
    for (int i = 0; i < 8; i++) {
        int idx = tid + i * NTHR;
        int r = idx >> 4, c = (idx & 15) * 4;
        cpa16(K0 + r * KS2 + c, g_kh + (size_t)r * D2 + h * 64 + c);
    }
    CP_COMMIT();

    unsigned qf[8][4];
    {
        const unsigned* qr0 = g_qh + (size_t)(q0 + rbase + g) * D2 + h * 64;
        const unsigned* qr1 = qr0 + 8 * D2;
#pragma unroll
        for (int ks = 0; ks < 8; ks++) {
            int kk2 = ks * 8;
            qf[ks][0] = qr0[kk2 + t];
            qf[ks][1] = qr1[kk2 + t];
            qf[ks][2] = qr0[kk2 + t + 4];
            qf[ks][3] = qr1[kk2 + t + 4];
        }
    }

    float o[16][4];
#pragma unroll
    for (int nt = 0; nt < 16; nt++)
#pragma unroll
        for (int i = 0; i < 4; i++) o[nt][i] = 0.f;
    float m0 = -1e30f, m1 = -1e30f, l0 = 0.f, l1 = 0.f;   // l: per-thread partials

    for (int kt = 0; kt < NT; kt++) {
        CP_WAIT0();
        __syncthreads();
        const int tok0 = kt * BKV;

#pragma unroll
        for (int i = 0; i < 8; i++) {
            int idx = tid + i * NTHR;
            int r = idx >> 3, c = (idx & 7) * 4;
            cpa16(Vs + r * VS2 + c,
                  vt32 + (size_t)(h * DH + r) * (SEQ / 2) + (tok0 >> 1) + c);
        }
        CP_COMMIT();
        if (kt + 1 < NT) {
            unsigned* Kn = K0 + ((kt + 1) & 1) * KSTG2;
#pragma unroll
            for (int i = 0; i < 8; i++) {
                int idx = tid + i * NTHR;
                int r = idx >> 4, c = (idx & 15) * 4;
                cpa16(Kn + r * KS2 + c,
                      g_kh + (size_t)(tok0 + BKV + r) * D2 + h * 64 + c);
            }
        }
        CP_COMMIT();

        const unsigned kb = kbase + ((kt & 1) ? KSTG2 * 4u : 0u) + kfoff;

        // ---- S = Q K^T ----
        float s[8][4];
#pragma unroll
        for (int nt = 0; nt < 8; nt++)
#pragma unroll
            for (int i = 0; i < 4; i++) s[nt][i] = 0.f;

#pragma unroll
        for (int ks = 0; ks < 8; ks++) {
#pragma unroll
            for (int n2 = 0; n2 < 4; n2++) {
                unsigned b[4];
                ldsm4(b[0], b[1], b[2], b[3],
                      kb + (unsigned)(n2 * 16 * KS2 + ks * 8) * 4);
                mma_f16(s[2 * n2],     qf[ks], b);
                mma_f16(s[2 * n2 + 1], qf[ks], b + 2);
            }
        }

        // ---- online softmax (base-2; quad max reduce only) ----
        float mx0 = -1e30f, mx1 = -1e30f;
#pragma unroll
        for (int nt = 0; nt < 8; nt++) {
            mx0 = fmaxf(mx0, fmaxf(s[nt][0], s[nt][1]));
            mx1 = fmaxf(mx1, fmaxf(s[nt][2], s[nt][3]));
        }
        mx0 = fmaxf(mx0, __shfl_xor_sync(0xffffffffu, mx0, 1));
        mx0 = fmaxf(mx0, __shfl_xor_sync(0xffffffffu, mx0, 2));
        mx1 = fmaxf(mx1, __shfl_xor_sync(0xffffffffu, mx1, 1));
        mx1 = fmaxf(mx1, __shfl_xor_sync(0xffffffffu, mx1, 2));

        float mn0 = fmaxf(m0, mx0), mn1 = fmaxf(m1, mx1);
        float al0 = ex2(m0 - mn0), al1 = ex2(m1 - mn1);
        float sum0 = 0.f, sum1 = 0.f;     // this thread's 8 columns only
#pragma unroll
        for (int nt = 0; nt < 8; nt++) {
            float p00 = ex2(s[nt][0] - mn0);
            float p01 = ex2(s[nt][1] - mn0);
            float p10 = ex2(s[nt][2] - mn1);
            float p11 = ex2(s[nt][3] - mn1);
            sum0 += p00 + p01; sum1 += p10 + p11;
            Ps[(rbase + g) * PS2 + nt * 4 + t]     = h2u(__floats2half2_rn(p00, p01));
            Ps[(rbase + g + 8) * PS2 + nt * 4 + t] = h2u(__floats2half2_rn(p10, p11));
        }
        l0 = l0 * al0 + sum0;             // per-thread partial recurrence
        l1 = l1 * al1 + sum1;
        m0 = mn0; m1 = mn1;
        if (al0 < 1.f || al1 < 1.f) {     // exact skip when both == 1
#pragma unroll
            for (int nt = 0; nt < 16; nt++) {
                o[nt][0] *= al0; o[nt][1] *= al0;
                o[nt][2] *= al1; o[nt][3] *= al1;
            }
        }

        CP_WAIT1();
        __syncthreads();

        // ---- O += P V ----
#pragma unroll
        for (int ks = 0; ks < 4; ks++) {
            unsigned a[4];
            ldsm4(a[0], a[1], a[2], a[3], pbase + (unsigned)(ks * 8) * 4);
#pragma unroll
            for (int n2 = 0; n2 < 8; n2++) {
                unsigned b[4];
                ldsm4(b[0], b[1], b[2], b[3],
                      vbase + (unsigned)(n2 * 16 * VS2 + ks * 8) * 4);
                mma_f16(o[2 * n2],     a, b);
                mma_f16(o[2 * n2 + 1], a, b + 2);
            }
        }
    }

    // final quad reduction of l (m is quad-uniform, so partials are aligned)
    l0 += __shfl_xor_sync(0xffffffffu, l0, 1);
    l0 += __shfl_xor_sync(0xffffffffu, l0, 2);
    l1 += __shfl_xor_sync(0xffffffffu, l1, 1);
    l1 += __shfl_xor_sync(0xffffffffu, l1, 2);

    const float inv0 = 1.0f / l0, inv1 = 1.0f / l1;
    const int r0 = q0 + rbase + g, r1 = r0 + 8;
#pragma unroll
    for (int nt = 0; nt < 16; nt++) {
        int c2 = h * 64 + nt * 4 + t;
        g_ath[(size_t)r0 * D2 + c2] =
            h2u(__floats2half2_rn(o[nt][0] * inv0, o[nt][1] * inv0));
        g_ath[(size_t)r1 * D2 + c2] =
            h2u(__floats2half2_rn(o[nt][2] * inv1, o[nt][3] * inv1));
    }
}

// ---------------------------------------------------------------------------
// Host launch
// ---------------------------------------------------------------------------
extern "C" void kernel_launch(void* const* d_in, const int* in_sizes, int n_in,
                              void* d_out, int out_size) {
    const float* x  = (const float*)d_in[0];
    const float* fc = (const float*)d_in[1];
    const float* fs = (const float*)d_in[2];
    const float* Wq = (const float*)d_in[3];
    const float* bq = (const float*)d_in[4];
    const float* Wk = (const float*)d_in[5];
    const float* bk = (const float*)d_in[6];
    const float* Wv = (const float*)d_in[7];
    const float* bv = (const float*)d_in[8];
    const float* Wo = (const float*)d_in[9];
    const float* bo = (const float*)d_in[10];
    const float* gq = (const float*)d_in[11];
    const float* gk = (const float*)d_in[12];
    float* out = (float*)d_out;

    cudaFuncSetAttribute(gemm_qkv_kernel, cudaFuncAttributeMaxDynamicSharedMemorySize,
                         GEMM_SMEM);
    cudaFuncSetAttribute(gemm_proj_kernel, cudaFuncAttributeMaxDynamicSharedMemorySize,
                         GEMM_SMEM);
    cudaFuncSetAttribute(attn_kernel, cudaFuncAttributeMaxDynamicSharedMemorySize,
                         ATTN_SMEM);

    pack_x_kernel<<<1024, 256>>>(x);
    packw_kernel<<<dim3(DIM / 32, DIM / 32, 4), 256>>>(Wq, Wk, Wv, Wo);

    gemm_qkv_kernel<<<dim3(DIM / BN, SEQ / BM, 3), 256, GEMM_SMEM>>>(bq, bk, bv);
    rmsnorm_rope_kernel<<<SEQ, 256>>>(fc, fs, gq, gk);
    attn_kernel<<<dim3(SEQ / BQ, NH), NTHR, ATTN_SMEM>>>();
    gemm_proj_kernel<<<dim3(DIM / BN, SEQ / BM), 256, GEMM_SMEM>>>(bo, out);
}